// round 16
// baseline (speedup 1.0000x reference)
#include <cuda_runtime.h>
#include <cstdint>

#define B_ 4
#define N_ 8192
#define C_ 64
#define K_ 16
#define O_ 128

#define NTILE 64                   // candidates per tile
#define NT2 (N_ / NTILE)           // 128 tiles
#define M_KEEP 20                  // filter margin (>=16)
#define F_ 12                      // FIFO slots per lane
#define NL 2                       // partial lists per query (column halves)
#define QS 20.0f                   // int8 quantization scale

// ---------------- scratch (no allocs allowed) ----------------
__device__ __align__(16) float    g_feats[B_ * N_ * C_];
__device__ __align__(16) float    g_xx[B_ * N_];
__device__ __align__(16) unsigned g_q8[B_ * N_ * 16];     // packed int8 feats (4/word)
__device__ __align__(16) int      g_xxq[B_ * N_];         // quantized sq norms
__device__ __align__(16) int      g_knn[B_ * N_ * K_];
__device__ __align__(16) float    g_pval[B_ * NL * N_ * M_KEEP];
__device__ __align__(16) int      g_pidx[B_ * NL * N_ * M_KEEP];
__device__ __align__(16) float    g_Y[B_ * N_ * O_];      // W2 . x_n
__device__ __align__(16) float    g_Z[B_ * N_ * O_];      // (W1-W2) . x_n

typedef unsigned long long u64;

// ---------------- packed f32x2 helpers (sm_103a) ----------------
__device__ __forceinline__ u64 fma2(u64 a, u64 b, u64 c) {
    u64 d;
    asm("fma.rn.f32x2 %0, %1, %2, %3;" : "=l"(d) : "l"(a), "l"(b), "l"(c));
    return d;
}
__device__ __forceinline__ u64 add2(u64 a, u64 b) {
    u64 d;
    asm("add.rn.f32x2 %0, %1, %2;" : "=l"(d) : "l"(a), "l"(b));
    return d;
}
__device__ __forceinline__ u64 dup2(float a) {
    u64 d;
    asm("mov.b64 %0, {%1, %1};" : "=l"(d) : "f"(a));
    return d;
}
__device__ __forceinline__ float psum(u64 v) {
    return __uint_as_float((unsigned)v) + __uint_as_float((unsigned)(v >> 32));
}
__device__ __forceinline__ uint32_t smem_u32(const void* p) {
    uint32_t a;
    asm("{ .reg .u64 t; cvta.to.shared.u64 t, %1; cvt.u32.u64 %0, t; }" : "=r"(a) : "l"(p));
    return a;
}
__device__ __forceinline__ void cp_async16(uint32_t dst, const void* src) {
    asm volatile("cp.async.cg.shared.global [%0], [%1], 16;" :: "r"(dst), "l"(src) : "memory");
}
__device__ __forceinline__ void cp_commit() {
    asm volatile("cp.async.commit_group;" ::: "memory");
}
__device__ __forceinline__ void cp_wait1() {
    asm volatile("cp.async.wait_group 1;" ::: "memory");
}
__device__ __forceinline__ void cp_wait0() {
    asm volatile("cp.async.wait_group 0;" ::: "memory");
}

// int8 tensor-core MMA (baseline PTX, legal on compute_103): D += A(16x32) B(32x8)
__device__ __forceinline__ void imma(int* c, const unsigned* a, const unsigned* b) {
    asm volatile(
        "mma.sync.aligned.m16n8k32.row.col.s32.s8.s8.s32 "
        "{%0,%1,%2,%3}, {%4,%5,%6,%7}, {%8,%9}, {%0,%1,%2,%3};"
        : "+r"(c[0]), "+r"(c[1]), "+r"(c[2]), "+r"(c[3])
        : "r"(a[0]), "r"(a[1]), "r"(a[2]), "r"(a[3]), "r"(b[0]), "r"(b[1]));
}

// predicated FIFO push (proven R13)
__device__ __forceinline__ void fifo_push(uint32_t fd_base, uint32_t fi_base,
                                          int cnt, int dv, int jj, int thr) {
    uint32_t off = (uint32_t)cnt << 10;    // cnt * 256 * 4
    asm volatile(
        "{\n\t.reg .pred p;\n\t"
        "setp.gt.s32 p, %0, %1;\n\t"
        "@p st.shared.b32 [%2], %0;\n\t"
        "@p st.shared.b32 [%3], %4;\n\t}"
        :: "r"(dv), "r"(thr), "r"(fd_base + off), "r"(fi_base + off), "r"(jj)
        : "memory");
}

// branch-free insert into descending sorted reg arrays (M_KEEP slots).
__device__ __forceinline__ void insM(int* mv, int* mi, int dv, int jj, bool live) {
    bool c[M_KEEP];
#pragma unroll
    for (int i = 0; i < M_KEEP; ++i) c[i] = live && (mv[i] < dv);
#pragma unroll
    for (int i = M_KEEP - 1; i >= 1; --i) {
        mv[i] = c[i - 1] ? mv[i - 1] : (c[i] ? dv : mv[i]);
        mi[i] = c[i - 1] ? mi[i - 1] : (c[i] ? jj : mi[i]);
    }
    mv[0] = c[0] ? dv : mv[0];
    mi[0] = c[0] ? jj : mi[0];
}

// ---------------- kernel 1: transpose, norms, int8 quantize ----------------
__global__ void __launch_bounds__(256) prep_kernel(const float* __restrict__ x) {
    int idx = blockIdx.x * 256 + threadIdx.x;      // 0 .. B*N-1
    int b = idx >> 13;
    int n = idx & (N_ - 1);
    const float* xb = x + (size_t)b * C_ * N_ + n;
    float v[C_];
    float acc = 0.f;
#pragma unroll
    for (int c = 0; c < C_; ++c) {
        float t = xb[(size_t)c * N_];              // coalesced across threads
        v[c] = t;
        acc = fmaf(t, t, acc);
    }
    float4* fp = reinterpret_cast<float4*>(g_feats + (size_t)idx * C_);
#pragma unroll
    for (int i = 0; i < C_ / 4; ++i)
        fp[i] = make_float4(v[4 * i], v[4 * i + 1], v[4 * i + 2], v[4 * i + 3]);

    unsigned pk[16];
    int xxq = 0;
#pragma unroll
    for (int g = 0; g < 16; ++g) {
        unsigned p = 0;
#pragma unroll
        for (int e = 0; e < 4; ++e) {
            float s = fminf(fmaxf(v[4 * g + e] * QS, -127.f), 127.f);
            int qi = __float2int_rn(s);
            xxq += qi * qi;
            p |= ((unsigned)qi & 0xFFu) << (8 * e);
        }
        pk[g] = p;
    }
    uint4* qp = reinterpret_cast<uint4*>(g_q8 + (size_t)idx * 16);
#pragma unroll
    for (int i = 0; i < 4; ++i)
        qp[i] = make_uint4(pk[4 * i], pk[4 * i + 1], pk[4 * i + 2], pk[4 * i + 3]);

    g_xxq[idx] = xxq;
    g_xx[idx] = acc;
}

// ---------------- kernel 2: imma KNN filter + exact fp32 rescore ----------------
// Grid (N/128, B_) = 256 CTAs, 256 threads, occ 2. CTA: 128 queries x all 8192 cands.
// smem layout (bytes):
#define S_A    0                          // A int8 tile 128x64 = 8192
#define S_B    8192                       // 2 x 4096 cand tiles
#define S_CXQ  16384                      // 2 x 64 ints
#define S_DIST 16896                      // 128 x 66 ints = 33792 (swizzled slots)
#define S_FD   50688                      // F_ x 256 ints
#define S_FI   62976                      // F_ x 256 ints
#define S_RMAX 75264                      // 2 x 128 ints = 1024
#define KNN_SMEM 76288

__global__ void __launch_bounds__(256, 2) knn_kernel() {
    extern __shared__ char smem[];
    uint32_t sb = smem_u32(smem);
    const int t = threadIdx.x;
    const int w = t >> 5;
    const int l = t & 31;
    const int gid = l >> 2;                // 0..7
    const int tig = l & 3;                 // 0..3
    const int b = blockIdx.y;
    const int q0 = blockIdx.x * 128;

    const int m0 = (w & 3) * 32;           // warp query-row base
    const int n0 = (w >> 2) * 32;          // warp cand-col base
    const int whalf = w >> 2;              // which column half this warp folds

    const unsigned* q8b = g_q8 + (size_t)b * N_ * 16;
    const int* xxqb = g_xxq + b * N_;

    int* s_cxq  = reinterpret_cast<int*>(smem + S_CXQ);
    int* s_fd   = reinterpret_cast<int*>(smem + S_FD);
    int* s_fi   = reinterpret_cast<int*>(smem + S_FI);
    int* s_rmax = reinterpret_cast<int*>(smem + S_RMAX);
    const uint32_t fd = sb + S_FD + t * 4;
    const uint32_t fi = sb + S_FI + t * 4;

    // ---- A tile load (once): 128 rows x 64B = 512 chunks ----
    {
        const char* asrc = reinterpret_cast<const char*>(q8b + (size_t)q0 * 16);
        cp_async16(sb + S_A + (uint32_t)t * 16, asrc + (size_t)t * 16);
        cp_async16(sb + S_A + (uint32_t)(t + 256) * 16, asrc + (size_t)(t + 256) * 16);
    }
    // ---- B tile loader: 64 rows x 64B = 256 chunks, 1 per thread ----
    auto issueB = [&](int tile, int buf) {
        const char* src = reinterpret_cast<const char*>(q8b + (size_t)(tile * NTILE) * 16);
        cp_async16(sb + S_B + buf * 4096 + (uint32_t)t * 16, src + (size_t)t * 16);
        cp_commit();
        if (t < NTILE) s_cxq[buf * NTILE + t] = xxqb[tile * NTILE + t];
    };
    issueB(0, 0);

    // per-thread query norms: rows m0 + mf*16 + gid (+8)
    int qn[4];
#pragma unroll
    for (int mf = 0; mf < 2; ++mf) {
        qn[mf * 2] = xxqb[q0 + m0 + mf * 16 + gid];
        qn[mf * 2 + 1] = xxqb[q0 + m0 + mf * 16 + gid + 8];
    }

    int mv[M_KEEP], mi[M_KEEP];
#pragma unroll
    for (int i = 0; i < M_KEEP; ++i) { mv[i] = (int)0x80000000; mi[i] = 0; }
    int thr = (int)0x80000000;
    int cnt = 0;

    cp_wait0();
    __syncthreads();                        // A + B[0] + cxq[0] visible

    // ---- persistent A fragments: af[mf][ks][4] ----
    unsigned af[2][2][4];
#pragma unroll
    for (int mf = 0; mf < 2; ++mf)
#pragma unroll
        for (int ks = 0; ks < 2; ++ks) {
            const char* ab = smem + S_A + (m0 + mf * 16 + gid) * 64 + ks * 32 + tig * 4;
            af[mf][ks][0] = *reinterpret_cast<const unsigned*>(ab);
            af[mf][ks][1] = *reinterpret_cast<const unsigned*>(ab + 512);   // row +8
            af[mf][ks][2] = *reinterpret_cast<const unsigned*>(ab + 16);    // k +16
            af[mf][ks][3] = *reinterpret_cast<const unsigned*>(ab + 512 + 16);
        }

    const int srow = t & 127;               // scan: query row
    const int shalf = t >> 7;               // scan: column half (32 cols)
    const int soff = 3 * (srow & 7);        // scan unswizzle offset
    int* dist = reinterpret_cast<int*>(smem + S_DIST);

    for (int tile = 0; tile < NT2; ++tile) {
        const int buf = tile & 1;
        if (tile + 1 < NT2) { issueB(tile + 1, buf ^ 1); cp_wait1(); }
        else                { cp_wait0(); }
        __syncthreads();                    // B(tile)+cxq ready; prev scan done (dist free)

        // ---- MMA: 2mf x 4nf x 2ks = 16 imma ----
        const char* Bt = smem + S_B + buf * 4096;
        int acc[2][4][4];
#pragma unroll
        for (int mf = 0; mf < 2; ++mf)
#pragma unroll
            for (int nf = 0; nf < 4; ++nf)
#pragma unroll
                for (int r = 0; r < 4; ++r) acc[mf][nf][r] = 0;

#pragma unroll
        for (int ks = 0; ks < 2; ++ks) {
            unsigned bf[4][2];
#pragma unroll
            for (int nf = 0; nf < 4; ++nf) {
                const char* bb = Bt + (n0 + nf * 8 + gid) * 64 + ks * 32 + tig * 4;
                bf[nf][0] = *reinterpret_cast<const unsigned*>(bb);
                bf[nf][1] = *reinterpret_cast<const unsigned*>(bb + 16);
            }
#pragma unroll
            for (int mf = 0; mf < 2; ++mf)
#pragma unroll
                for (int nf = 0; nf < 4; ++nf)
                    imma(acc[mf][nf], af[mf][ks], bf[nf]);
        }

        // ---- fold: d = 2*acc - qxx - cxx -> swizzled dist + per-row running max ----
        int rm[4];
#pragma unroll
        for (int r = 0; r < 4; ++r) rm[r] = (int)0x80000000;
#pragma unroll
        for (int nf = 0; nf < 4; ++nf) {
            int col = n0 + nf * 8 + tig * 2;
            int c2 = col >> 1;
            int slot = (c2 + 3 * gid) & 31;        // conflict-free STS mapping
            int2 cx2 = *reinterpret_cast<const int2*>(s_cxq + buf * NTILE + col);
#pragma unroll
            for (int mf = 0; mf < 2; ++mf) {
                int row = m0 + mf * 16 + gid;
                int2 dlo, dhi;
                dlo.x = (acc[mf][nf][0] << 1) - qn[mf * 2] - cx2.x;
                dlo.y = (acc[mf][nf][1] << 1) - qn[mf * 2] - cx2.y;
                dhi.x = (acc[mf][nf][2] << 1) - qn[mf * 2 + 1] - cx2.x;
                dhi.y = (acc[mf][nf][3] << 1) - qn[mf * 2 + 1] - cx2.y;
                *reinterpret_cast<int2*>(dist + row * 66 + slot * 2) = dlo;
                *reinterpret_cast<int2*>(dist + (row + 8) * 66 + slot * 2) = dhi;
                rm[mf * 2] = max(rm[mf * 2], max(dlo.x, dlo.y));
                rm[mf * 2 + 1] = max(rm[mf * 2 + 1], max(dhi.x, dhi.y));
            }
        }
        // reduce rm over tig (lanes gid*4+tig) and publish per (row, half)
#pragma unroll
        for (int r = 0; r < 4; ++r) {
            rm[r] = max(rm[r], __shfl_xor_sync(0xffffffffu, rm[r], 1));
            rm[r] = max(rm[r], __shfl_xor_sync(0xffffffffu, rm[r], 2));
        }
        if (tig == 0) {
            s_rmax[whalf * 128 + m0 + gid] = rm[0];
            s_rmax[whalf * 128 + m0 + gid + 8] = rm[1];
            s_rmax[whalf * 128 + m0 + 16 + gid] = rm[2];
            s_rmax[whalf * 128 + m0 + 24 + gid] = rm[3];
        }
        __syncthreads();                    // dist + rowmax complete

        // ---- scan: rowmax-gated; thread owns (srow, 32-col half) ----
        {
            const bool act = s_rmax[shalf * 128 + srow] > thr;
            const int cbase = tile * NTILE + shalf * 32;
            const int* drow = dist + srow * 66;
#pragma unroll 1
            for (int jb = 0; jb < 4; ++jb) {
                if (act) {
                    int d[8];
#pragma unroll
                    for (int e = 0; e < 4; ++e) {
                        int c2 = shalf * 16 + jb * 4 + e;
                        int sl = (c2 + soff) & 31;
                        int2 v = *reinterpret_cast<const int2*>(drow + sl * 2);
                        d[2 * e] = v.x;
                        d[2 * e + 1] = v.y;
                    }
                    int dmax = d[0];
#pragma unroll
                    for (int e = 1; e < 8; ++e) dmax = max(dmax, d[e]);
                    if (dmax > thr) {       // rare (R11-proven guard)
#pragma unroll
                        for (int e = 0; e < 8; ++e) {
                            fifo_push(fd, fi, cnt, d[e], cbase + jb * 8 + e, thr);
                            cnt += (d[e] > thr) ? 1 : 0;
                        }
                    }
                }
                // uniform-mask flush check (all lanes converge here)
                if (__any_sync(0xffffffffu, cnt > F_ - 8)) {
                    int m = (int)__reduce_max_sync(0xffffffffu, (unsigned)cnt);
#pragma unroll 1
                    for (int e = 0; e < m; ++e)
                        insM(mv, mi, s_fd[e * 256 + t], s_fi[e * 256 + t], e < cnt);
                    thr = mv[M_KEEP - 1];
                    cnt = 0;
                }
            }
        }
        // loop-top __syncthreads separates this scan from next fold
    }

    // final flush
    {
        int m = (int)__reduce_max_sync(0xffffffffu, (unsigned)cnt);
#pragma unroll 1
        for (int e = 0; e < m; ++e)
            insM(mv, mi, s_fd[e * 256 + t], s_fi[e * 256 + t], e < cnt);
    }

    // ---- exact fp32 rescore (proven path) ----
    const int q = q0 + srow;
    float fv[M_KEEP];
    {
        const float* fbf = g_feats + (size_t)b * N_ * C_;
        const float* xxb = g_xx + b * N_;
        const u64* qp = reinterpret_cast<const u64*>(fbf + (size_t)q * C_);
        u64 qv2[32];
#pragma unroll
        for (int i = 0; i < 32; ++i) qv2[i] = qp[i];
        float qxxe = xxb[q];
#pragma unroll
        for (int i = 0; i < M_KEEP; ++i) {
            int idx = mi[i];
            const u64* cp = reinterpret_cast<const u64*>(fbf + (size_t)idx * C_);
            u64 a0 = 0, a1 = 0, a2 = 0, a3 = 0;
#pragma unroll
            for (int j = 0; j < 8; ++j) {
                a0 = fma2(qv2[4 * j + 0], cp[4 * j + 0], a0);
                a1 = fma2(qv2[4 * j + 1], cp[4 * j + 1], a1);
                a2 = fma2(qv2[4 * j + 2], cp[4 * j + 2], a2);
                a3 = fma2(qv2[4 * j + 3], cp[4 * j + 3], a3);
            }
            float inner = psum(add2(add2(a0, a1), add2(a2, a3)));
            fv[i] = 2.f * inner - qxxe - xxb[idx];
        }
    }

    // odd-even sort by (val desc, idx asc)
#pragma unroll
    for (int pass = 0; pass < M_KEEP; ++pass) {
#pragma unroll
        for (int i = (pass & 1); i + 1 < M_KEEP; i += 2) {
            bool sw = (fv[i + 1] > fv[i]) || (fv[i + 1] == fv[i] && mi[i + 1] < mi[i]);
            float tv = sw ? fv[i + 1] : fv[i];
            fv[i + 1] = sw ? fv[i] : fv[i + 1];
            fv[i] = tv;
            int ti = sw ? mi[i + 1] : mi[i];
            mi[i + 1] = sw ? mi[i] : mi[i + 1];
            mi[i] = ti;
        }
    }

    // write partial list (list id = b*NL + shalf)
    {
        size_t L = (size_t)(b * NL + shalf);
        float* pv = g_pval + (L * N_ + q) * M_KEEP;
        int*   pi = g_pidx + (L * N_ + q) * M_KEEP;
#pragma unroll
        for (int i = 0; i < M_KEEP; ++i) { pv[i] = fv[i]; pi[i] = mi[i]; }
    }
}

// ---------------- kernel 2b: NL-way merge of partial top lists ----------------
__global__ void __launch_bounds__(256) merge_kernel() {
    int id = blockIdx.x * 256 + threadIdx.x;       // 0 .. B*N-1
    int b = id >> 13;
    int q = id & (N_ - 1);

    const float* pv[NL];
    const int*   pi[NL];
    float hv[NL];
    int   hx[NL];
    int   cur[NL];
#pragma unroll
    for (int c = 0; c < NL; ++c) {
        pv[c] = g_pval + (((size_t)(b * NL + c)) * N_ + q) * M_KEEP;
        pi[c] = g_pidx + (((size_t)(b * NL + c)) * N_ + q) * M_KEEP;
        hv[c] = pv[c][0];
        hx[c] = pi[c][0];
        cur[c] = 0;
    }
    int* og = g_knn + (size_t)id * K_;
#pragma unroll
    for (int s = 0; s < 16; ++s) {
        int best = 0;
#pragma unroll
        for (int c = 1; c < NL; ++c)
            if (hv[c] > hv[best] || (hv[c] == hv[best] && hx[c] < hx[best])) best = c;
        og[s] = hx[best];
        if (++cur[best] < M_KEEP) {
            hv[best] = pv[best][cur[best]];
            hx[best] = pi[best][cur[best]];
        } else {
            hv[best] = -3.4e38f;
            hx[best] = 0x7fffffff;
        }
    }
}

// ---------------- kernel 3a: per-point GEMM  Y = W2.x, Z = (W1-W2).x ----------------
__global__ void __launch_bounds__(128) zy_kernel(const float* __restrict__ W) {
    __shared__ __align__(16) float s_x[64 * C_];    // 16 KB point tile
    const int t = threadIdx.x;                      // channel
    const int b = blockIdx.y;
    const int p0 = blockIdx.x * 64;

    {
        uint32_t dst = smem_u32(s_x);
        const char* src = reinterpret_cast<const char*>(g_feats + ((size_t)b * N_ + p0) * C_);
#pragma unroll
        for (int i = 0; i < 8; ++i) {
            int c = t + i * 128;
            cp_async16(dst + (uint32_t)c * 16, src + (size_t)c * 16);
        }
        cp_commit();
    }

    u64 w2r[32], wzr[32];
    {
        const u64* wp = reinterpret_cast<const u64*>(W + (size_t)t * 2 * C_);
        const u64 neg1 = dup2(-1.f);
#pragma unroll
        for (int i = 0; i < 32; ++i) {
            u64 w1 = wp[i];
            u64 w2 = wp[32 + i];
            w2r[i] = w2;
            wzr[i] = fma2(w2, neg1, w1);            // w1 - w2 (exact)
        }
    }

    float* Yb = g_Y + ((size_t)b * N_ + p0) * O_;
    float* Zb = g_Z + ((size_t)b * N_ + p0) * O_;

    cp_wait0();
    __syncthreads();

#pragma unroll 1
    for (int pl = 0; pl < 64; ++pl) {
        const ulonglong2* xp = reinterpret_cast<const ulonglong2*>(s_x + pl * C_);
        u64 y0 = 0, y1 = 0, y2 = 0, y3 = 0;
        u64 z0 = 0, z1 = 0, z2 = 0, z3 = 0;
#pragma unroll
        for (int i = 0; i < 8; ++i) {
            ulonglong2 ua = xp[2 * i];
            ulonglong2 ub = xp[2 * i + 1];
            y0 = fma2(w2r[4 * i + 0], ua.x, y0);
            y1 = fma2(w2r[4 * i + 1], ua.y, y1);
            y2 = fma2(w2r[4 * i + 2], ub.x, y2);
            y3 = fma2(w2r[4 * i + 3], ub.y, y3);
            z0 = fma2(wzr[4 * i + 0], ua.x, z0);
            z1 = fma2(wzr[4 * i + 1], ua.y, z1);
            z2 = fma2(wzr[4 * i + 2], ub.x, z2);
            z3 = fma2(wzr[4 * i + 3], ub.y, z3);
        }
        Yb[pl * O_ + t] = psum(add2(add2(y0, y1), add2(y2, y3)));
        Zb[pl * O_ + t] = psum(add2(add2(z0, z1), add2(z2, z3)));
    }
}

// ---------------- kernel 3b: gather-max epilogue ----------------
#define GPB 64
__global__ void __launch_bounds__(128) gmax_kernel(const float* __restrict__ bias,
                                                   float* __restrict__ out) {
    __shared__ int   s_nidx[GPB * K_];
    __shared__ float s_res[128 * 65];

    const int t = threadIdx.x;                      // channel
    const int b = blockIdx.y;
    const int p0 = blockIdx.x * GPB;

    const float* Yb = g_Y + (size_t)b * N_ * O_;
    const float* Zb = g_Z + (size_t)b * N_ * O_;
    const float bo = bias[t];

    for (int i = t; i < GPB * K_; i += 128)
        s_nidx[i] = g_knn[(size_t)(b * N_ + p0) * K_ + i];
    __syncthreads();

#pragma unroll 1
    for (int pl = 0; pl < GPB; ++pl) {
        const int* nn = s_nidx + pl * K_;
        float m = -3.4e38f;
#pragma unroll
        for (int k = 0; k < K_; ++k)
            m = fmaxf(m, Yb[(size_t)nn[k] * O_ + t]);
        float z = Zb[(size_t)(p0 + pl) * O_ + t];
        s_res[t * 65 + pl] = z + m + bo;
    }
    __syncthreads();

#pragma unroll
    for (int i = 0; i < 64; ++i) {
        int idx = t + i * 128;
        int o = idx >> 6;
        int p = idx & 63;
        out[((size_t)(b * O_ + o)) * N_ + p0 + p] = s_res[o * 65 + p];
    }
}

// ---------------- launch ----------------
extern "C" void kernel_launch(void* const* d_in, const int* in_sizes, int n_in,
                              void* d_out, int out_size) {
    (void)in_sizes; (void)n_in; (void)out_size;
    const float* x    = (const float*)d_in[0];   // (4, 64, 8192, 1)
    const float* W    = (const float*)d_in[1];   // (128, 128)
    const float* bias = (const float*)d_in[2];   // (128,)
    float* out = (float*)d_out;                  // (4, 128, 8192, 1)

    cudaFuncSetAttribute(knn_kernel, cudaFuncAttributeMaxDynamicSharedMemorySize, KNN_SMEM);

    prep_kernel<<<(B_ * N_) / 256, 256>>>(x);
    knn_kernel<<<dim3(N_ / 128, B_), 256, KNN_SMEM>>>();
    merge_kernel<<<(B_ * N_) / 256, 256>>>();
    zy_kernel<<<dim3(N_ / 64, B_), 128>>>(W);
    gmax_kernel<<<dim3(N_ / GPB, B_), 128>>>(bias, out);
}